// round 6
// baseline (speedup 1.0000x reference)
#include <cuda_runtime.h>
#include <cstdint>

#define ENTITYN 50000
#define EMBD    256
#define HIDD    256
#define BATCHN  64
#define LSEQ    256
#define NEDGE   800000

// ---------------- scratch (device globals: no allocation allowed) ----------------
__device__ float g_bufA[BATCHN * LSEQ * HIDD];        // 16.8 MB
__device__ float g_bufB[BATCHN * LSEQ * HIDD];        // 16.8 MB
__device__ float g_xi[BATCHN * LSEQ * 3 * HIDD];      // 50 MB
__device__ float g_WihT[HIDD * 3 * HIDD];             // [k][n] = Wih[n][k]
__device__ float g_fc1WT[HIDD * HIDD];                // [k][j] = fc1W[j][k]
__device__ float g_support[ENTITYN * HIDD];           // 51.2 MB (gated path)
__device__ float g_agg[ENTITYN * HIDD];               // 51.2 MB (gated path)
__device__ float g_hT[BATCHN * HIDD];
__device__ float g_hx[2][BATCHN][HIDD];               // GRU h double buffer (128 KB)
__device__ unsigned int g_sync[16];                   // per-group arrival counters

// Device-side buffer selector: keeps kernel_launch free of cudaGetSymbolAddress.
#define SEL_EXT     0
#define SEL_BUFA    1
#define SEL_BUFB    2
#define SEL_XI      3
#define SEL_WIHT    4
#define SEL_SUPPORT 5

__device__ __forceinline__ float* selptr(int s, const void* ext) {
    switch (s) {
        case SEL_BUFA:    return g_bufA;
        case SEL_BUFB:    return g_bufB;
        case SEL_XI:      return g_xi;
        case SEL_WIHT:    return g_WihT;
        case SEL_SUPPORT: return g_support;
        default:          return (float*)ext;
    }
}

__device__ __forceinline__ uint32_t f2tf32(float x) {
    uint32_t u;
    asm("cvt.rna.tf32.f32 %0, %1;" : "=r"(u) : "f"(x));
    return u;
}

__device__ __forceinline__ void mma_tf32(float* c, const uint32_t* a,
                                         uint32_t b0, uint32_t b1) {
    asm volatile(
        "mma.sync.aligned.m16n8k8.row.col.f32.tf32.tf32.f32 "
        "{%0,%1,%2,%3}, {%4,%5,%6,%7}, {%8,%9}, {%0,%1,%2,%3};"
        : "+f"(c[0]), "+f"(c[1]), "+f"(c[2]), "+f"(c[3])
        : "r"(a[0]), "r"(a[1]), "r"(a[2]), "r"(a[3]), "r"(b0), "r"(b1));
}

// ---------------- weight prep: transposes + sync-counter reset ----------------
__global__ void prep_kernel(const float* __restrict__ Wih,
                            const float* __restrict__ fc1W) {
    int stride = gridDim.x * blockDim.x;
    int t0 = blockIdx.x * blockDim.x + threadIdx.x;
    if (t0 < 16) g_sync[t0] = 0u;      // reset GRU barrier counters every launch
    for (int i = t0; i < 256 * 768; i += stride) {
        int k = i / 768, n = i % 768;
        g_WihT[i] = Wih[n * 256 + k];
    }
    for (int i = t0; i < 256 * 256; i += stride) {
        int k = i / 256, j = i % 256;
        g_fc1WT[i] = fc1W[j * 256 + k];
    }
}

// ---------------- gated GNN path (only runs when eps != 0) ----------------
__global__ void zero_agg_kernel(const float* __restrict__ eps) {
    if (eps[0] == 0.0f) return;
    int stride = gridDim.x * blockDim.x;
    for (int i = blockIdx.x * blockDim.x + threadIdx.x; i < ENTITYN * HIDD; i += stride)
        g_agg[i] = 0.0f;
}

__global__ void scatter_kernel(const int* __restrict__ esrc,
                               const int* __restrict__ edst,
                               const float* __restrict__ ew,
                               const float* __restrict__ eps) {
    if (eps[0] == 0.0f) return;
    long stride = (long)gridDim.x * blockDim.x;
    long total = (long)NEDGE * 64;
    for (long i = (long)blockIdx.x * blockDim.x + threadIdx.x; i < total; i += stride) {
        int e = (int)(i >> 6);
        int c = ((int)i & 63) * 4;
        int s = esrc[e], d = edst[e];
        float w = ew[e];
        const float4 v = *(const float4*)&g_support[(long)s * 256 + c];
        float* dst = &g_agg[(long)d * 256 + c];
        atomicAdd(dst + 0, v.x * w);
        atomicAdd(dst + 1, v.y * w);
        atomicAdd(dst + 2, v.z * w);
        atomicAdd(dst + 3, v.w * w);
    }
}

// ---------------- tf32 tensor-core GEMM (unchanged from R4, passing) ----------------
__global__ void __launch_bounds__(256, 2) mma_gemm_kernel(
    int selA, const void* Aext, long strideA,
    int selB, const void* Bext, long strideB,
    int selC, void* Cext, long strideC,
    const float* __restrict__ bias,
    const int* __restrict__ gidx,
    const float* __restrict__ gate,
    int M, int N, int K)
{
    if (gate != nullptr && gate[0] == 0.0f) return;
    const float* A = selptr(selA, Aext) + (long)blockIdx.z * strideA;
    const float* B = selptr(selB, Bext) + (long)blockIdx.z * strideB;
    float*       C = selptr(selC, Cext) + (long)blockIdx.z * strideC;

    __shared__ uint32_t As[128][36];
    __shared__ uint32_t Bs[32][132];

    const int tid  = threadIdx.x;
    const int wid  = tid >> 5, lane = tid & 31;
    const int g    = lane >> 2, t = lane & 3;
    const int wm   = wid >> 1, wn = wid & 1;
    const int m0   = blockIdx.y * 128, n0 = blockIdx.x * 128;

    long agrow[4];
#pragma unroll
    for (int i = 0; i < 4; i++) {
        int f = tid + i * 256;
        int m = m0 + (f >> 3);
        if (m < M) agrow[i] = gidx ? (long)gidx[m] : (long)m;
        else       agrow[i] = -1;
    }

    float acc[2][8][4];
#pragma unroll
    for (int mt = 0; mt < 2; mt++)
#pragma unroll
        for (int nt = 0; nt < 8; nt++)
#pragma unroll
            for (int q = 0; q < 4; q++) acc[mt][nt][q] = 0.0f;

    for (int k0 = 0; k0 < K; k0 += 32) {
#pragma unroll
        for (int i = 0; i < 4; i++) {
            int f = tid + i * 256;
            int row = f >> 3, k4 = (f & 7) * 4;
            float4 v = make_float4(0.f, 0.f, 0.f, 0.f);
            if (agrow[i] >= 0) v = *(const float4*)(A + agrow[i] * K + k0 + k4);
            uint4 u = make_uint4(f2tf32(v.x), f2tf32(v.y), f2tf32(v.z), f2tf32(v.w));
            *(uint4*)&As[row][k4] = u;
        }
#pragma unroll
        for (int i = 0; i < 4; i++) {
            int f = tid + i * 256;
            int kk = f >> 5, n4 = (f & 31) * 4;
            float4 v = *(const float4*)(B + (long)(k0 + kk) * N + n0 + n4);
            uint4 u = make_uint4(f2tf32(v.x), f2tf32(v.y), f2tf32(v.z), f2tf32(v.w));
            *(uint4*)&Bs[kk][n4] = u;
        }
        __syncthreads();

#pragma unroll
        for (int ks = 0; ks < 32; ks += 8) {
            uint32_t af[2][4];
#pragma unroll
            for (int mt = 0; mt < 2; mt++) {
                int r = wm * 32 + mt * 16 + g;
                af[mt][0] = As[r    ][ks + t];
                af[mt][1] = As[r + 8][ks + t];
                af[mt][2] = As[r    ][ks + t + 4];
                af[mt][3] = As[r + 8][ks + t + 4];
            }
#pragma unroll
            for (int nt = 0; nt < 8; nt++) {
                int c = wn * 64 + nt * 8 + g;
                uint32_t b0 = Bs[ks + t    ][c];
                uint32_t b1 = Bs[ks + t + 4][c];
                mma_tf32(acc[0][nt], af[0], b0, b1);
                mma_tf32(acc[1][nt], af[1], b0, b1);
            }
        }
        __syncthreads();
    }

#pragma unroll
    for (int mt = 0; mt < 2; mt++) {
        int r0 = m0 + wm * 32 + mt * 16 + g;
#pragma unroll
        for (int nt = 0; nt < 8; nt++) {
            int c = n0 + wn * 64 + nt * 8 + 2 * t;
            float b0v = 0.f, b1v = 0.f;
            if (bias) { b0v = bias[c]; b1v = bias[c + 1]; }
            if (r0 < M) {
                float2 o = make_float2(acc[mt][nt][0] + b0v, acc[mt][nt][1] + b1v);
                *(float2*)(C + (long)r0 * N + c) = o;
            }
            int r1 = r0 + 8;
            if (r1 < M) {
                float2 o = make_float2(acc[mt][nt][2] + b0v, acc[mt][nt][3] + b1v);
                *(float2*)(C + (long)r1 * N + c) = o;
            }
        }
    }
}

// ---------------- eps mix ----------------
__global__ void mix_kernel(const int* __restrict__ cur,
                           const float* __restrict__ bg,
                           const float* __restrict__ eps) {
    float e = eps[0];
    int stride = gridDim.x * blockDim.x;
    for (int i = blockIdx.x * blockDim.x + threadIdx.x; i < BATCHN * LSEQ * HIDD; i += stride) {
        float v = g_bufB[i];
        if (e != 0.0f) {
            int row = i >> 8, col = i & 255;
            int cn = cur[row];
            float a = g_agg[(long)cn * 256 + col] + bg[col];
            a = a > 0.0f ? a : 0.2f * a;
            v = (1.0f - e) * v + e * a;
        }
        g_bufA[i] = v;
    }
}

// ---------------- GRU: 16 groups x 8 CTAs, weights register-resident,
// h exchanged through global double buffer + per-group atomic barrier.
// Group c owns batches [4c,4c+4); CTA rank r owns hidden slice [32r,32r+32)
// (96 gate rows). Thread (lrow,kq): 64 weights of one gate row. No clusters.
__global__ void __launch_bounds__(384, 1)
gru_sync_kernel(const float* __restrict__ Whh,
                const float* __restrict__ bhh) {
    __shared__ __align__(16) float hs[4][256];
    __shared__ float gh[96][4];
    __shared__ float sbl[96];

    const int tid  = threadIdx.x;
    const int cid  = blockIdx.x >> 3;
    const int rank = blockIdx.x & 7;
    const int j0   = rank * 32;

    const int lrow = tid >> 2;            // 0..95
    const int kq   = tid & 3;             // k-chunk 0..3
    const int gate = lrow >> 5;           // 0=r,1=z,2=n
    const int jj   = lrow & 31;
    const int grow = gate * 256 + j0 + jj;
    const int k0   = kq * 64;

    // weights -> registers (coalesced float4 from row-major Whh)
    float w[64];
    {
        const float4* wsrc = (const float4*)(Whh + (long)grow * 256 + k0);
#pragma unroll
        for (int i = 0; i < 16; i++) {
            float4 v = wsrc[i];
            w[i * 4 + 0] = v.x; w[i * 4 + 1] = v.y;
            w[i * 4 + 2] = v.z; w[i * 4 + 3] = v.w;
        }
    }
    if (tid < 96) sbl[tid] = bhh[(tid >> 5) * 256 + j0 + (tid & 31)];

    const int ejj = tid >> 2, eb = tid & 3;   // epilogue mapping (tid<128)
    unsigned int* cnt = &g_sync[cid];

    // init: write h0 = 0 into buffer 0 (each CTA writes its exclusive slice)
    if (tid < 128) {
        g_hx[0][cid * 4 + eb][j0 + ejj] = 0.0f;
        __threadfence();
    }
    __syncthreads();
    if (tid == 0) atomicAdd(cnt, 1u);

    for (int t = 0; t < 256; t++) {
        const int p = t & 1;
        // prefetch xi (DRAM latency hidden behind spin + h-load)
        float xr = 0.f, xz = 0.f, xn = 0.f;
        if (tid < 128) {
            const float* xb = g_xi + (((long)(cid * 4 + eb) * 256 + t) * 768);
            xr = xb[j0 + ejj];
            xz = xb[256 + j0 + ejj];
            xn = xb[512 + j0 + ejj];
        }
        // group barrier: wait until all 8 CTAs published h_t
        if (tid == 0) {
            const unsigned int target = 8u * (unsigned)(t + 1);
            unsigned int v;
            do {
                asm volatile("ld.global.acquire.gpu.u32 %0, [%1];"
                             : "=r"(v) : "l"(cnt));
                if (v >= target) break;
                __nanosleep(32);
            } while (true);
        }
        __syncthreads();

        // cooperative load h_t (4x256) into smem, L2-coherent path
        if (tid < 256) {
            const float4* src = (const float4*)&g_hx[p][cid * 4][0];
            ((float4*)hs)[tid] = __ldcg(src + tid);
        }
        __syncthreads();

        // gh slice: 96 gate rows x 4 batches
        float acc0 = 0.f, acc1 = 0.f, acc2 = 0.f, acc3 = 0.f;
#pragma unroll
        for (int k4 = 0; k4 < 16; k4++) {
            float4 h0 = *(const float4*)&hs[0][k0 + k4 * 4];
            float4 h1 = *(const float4*)&hs[1][k0 + k4 * 4];
            float4 h2 = *(const float4*)&hs[2][k0 + k4 * 4];
            float4 h3 = *(const float4*)&hs[3][k0 + k4 * 4];
            float w0 = w[k4 * 4 + 0], w1 = w[k4 * 4 + 1];
            float w2 = w[k4 * 4 + 2], w3 = w[k4 * 4 + 3];
            acc0 += w0 * h0.x + w1 * h0.y + w2 * h0.z + w3 * h0.w;
            acc1 += w0 * h1.x + w1 * h1.y + w2 * h1.z + w3 * h1.w;
            acc2 += w0 * h2.x + w1 * h2.y + w2 * h2.z + w3 * h2.w;
            acc3 += w0 * h3.x + w1 * h3.y + w2 * h3.z + w3 * h3.w;
        }
        acc0 += __shfl_xor_sync(0xFFFFFFFFu, acc0, 1);
        acc0 += __shfl_xor_sync(0xFFFFFFFFu, acc0, 2);
        acc1 += __shfl_xor_sync(0xFFFFFFFFu, acc1, 1);
        acc1 += __shfl_xor_sync(0xFFFFFFFFu, acc1, 2);
        acc2 += __shfl_xor_sync(0xFFFFFFFFu, acc2, 1);
        acc2 += __shfl_xor_sync(0xFFFFFFFFu, acc2, 2);
        acc3 += __shfl_xor_sync(0xFFFFFFFFu, acc3, 1);
        acc3 += __shfl_xor_sync(0xFFFFFFFFu, acc3, 2);
        if (kq == 0) {
            gh[lrow][0] = acc0; gh[lrow][1] = acc1;
            gh[lrow][2] = acc2; gh[lrow][3] = acc3;
        }
        __syncthreads();

        if (tid < 128) {
            float hr = gh[ejj][eb]      + sbl[ejj];
            float hz = gh[32 + ejj][eb] + sbl[32 + ejj];
            float hn = gh[64 + ejj][eb] + sbl[64 + ejj];
            float hprev = hs[eb][j0 + ejj];
            float r = 1.0f / (1.0f + __expf(-(xr + hr)));
            float z = 1.0f / (1.0f + __expf(-(xz + hz)));
            float n = tanhf(xn + r * hn);
            float hnew = (1.0f - z) * n + z * hprev;

            __stcg(&g_hx[1 - p][cid * 4 + eb][j0 + ejj], hnew);
            if (t == 255)
                g_hT[(long)(cid * 4 + eb) * 256 + j0 + ejj] = hnew;
            __threadfence();   // publish before arrival
        }
        __syncthreads();
        if (tid == 0) atomicAdd(cnt, 1u);
    }
}

// ---------------- final fc1 + relu ----------------
__global__ void fc_kernel(const float* __restrict__ fc1b, float* __restrict__ out) {
    __shared__ float hsf[HIDD];
    const int b = blockIdx.x, j = threadIdx.x;
    hsf[j] = g_hT[b * HIDD + j];
    __syncthreads();
    float acc = 0.0f;
#pragma unroll 8
    for (int k = 0; k < HIDD; k++) acc += hsf[k] * g_fc1WT[k * HIDD + j];
    acc += fc1b[j];
    out[b * HIDD + j] = acc > 0.0f ? acc : 0.0f;
}

// ---------------- launcher: kernel launches ONLY, no other CUDA API ----------------
extern "C" void kernel_launch(void* const* d_in, const int* in_sizes, int n_in,
                              void* d_out, int out_size) {
    const int*   neighbors = (const int*)  d_in[0];
    const float* adj       = (const float*)d_in[1];
    const int*   cur_node  = (const int*)  d_in[2];
    const int*   edge_src  = (const int*)  d_in[3];
    const int*   edge_dst  = (const int*)  d_in[4];
    const float* edge_w    = (const float*)d_in[5];
    const float* emb       = (const float*)d_in[6];
    const float* Wg        = (const float*)d_in[7];
    const float* bg        = (const float*)d_in[8];
    const float* W1        = (const float*)d_in[9];
    const float* b1        = (const float*)d_in[10];
    const float* W2        = (const float*)d_in[11];
    const float* b2        = (const float*)d_in[12];
    const float* eps       = (const float*)d_in[13];
    const float* Wih       = (const float*)d_in[14];
    const float* Whh       = (const float*)d_in[15];
    const float* bih       = (const float*)d_in[16];
    const float* bhh       = (const float*)d_in[17];
    const float* fc1W      = (const float*)d_in[18];
    const float* fc1b      = (const float*)d_in[19];
    float* out = (float*)d_out;

    const int  MBL  = BATCHN * LSEQ;        // 16384
    const long SADJ = (long)LSEQ * LSEQ;    // 65536
    const long SX   = (long)LSEQ * HIDD;    // 65536

    // weight prep + GRU barrier reset
    prep_kernel<<<256, 256>>>(Wih, fc1W);

    // gated global-GNN path (no-op when eps == 0)
    zero_agg_kernel<<<2048, 256>>>(eps);
    mma_gemm_kernel<<<dim3(2, (ENTITYN + 127) / 128, 1), 256>>>(
        SEL_EXT, emb, 0, SEL_EXT, Wg, 0, SEL_SUPPORT, nullptr, 0,
        nullptr, nullptr, eps, ENTITYN, 256, 256);
    scatter_kernel<<<4096, 256>>>(edge_src, edge_dst, edge_w, eps);

    // bufA = emb[neighbors] @ W1
    mma_gemm_kernel<<<dim3(2, MBL / 128, 1), 256>>>(
        SEL_EXT, emb, 0, SEL_EXT, W1, 0, SEL_BUFA, nullptr, 0,
        nullptr, neighbors, nullptr, MBL, 256, 256);
    // bufB = adj @ bufA + b1   (batched over 64)
    mma_gemm_kernel<<<dim3(2, 2, 64), 256>>>(
        SEL_EXT, adj, SADJ, SEL_BUFA, nullptr, SX, SEL_BUFB, nullptr, SX,
        b1, nullptr, nullptr, 256, 256, 256);
    // bufA = bufB @ W2
    mma_gemm_kernel<<<dim3(2, MBL / 128, 1), 256>>>(
        SEL_BUFB, nullptr, 0, SEL_EXT, W2, 0, SEL_BUFA, nullptr, 0,
        nullptr, nullptr, nullptr, MBL, 256, 256);
    // bufB = adj @ bufA + b2
    mma_gemm_kernel<<<dim3(2, 2, 64), 256>>>(
        SEL_EXT, adj, SADJ, SEL_BUFA, nullptr, SX, SEL_BUFB, nullptr, SX,
        b2, nullptr, nullptr, 256, 256, 256);
    // bufA = mix(bufB, eps, agg[cur]+bg)
    mix_kernel<<<2048, 256>>>(cur_node, bg, eps);
    // xi = bufA @ WihT + bih
    mma_gemm_kernel<<<dim3(6, MBL / 128, 1), 256>>>(
        SEL_BUFA, nullptr, 0, SEL_WIHT, nullptr, 0, SEL_XI, nullptr, 0,
        bih, nullptr, nullptr, MBL, 768, 256);
    // GRU recurrence: 128 CTAs, register-resident weights, global barrier
    gru_sync_kernel<<<128, 384>>>(Whh, bhh);
    // out = relu(hT @ fc1W^T + fc1b)
    fc_kernel<<<64, 256>>>(fc1b, out);
}